// round 6
// baseline (speedup 1.0000x reference)
#include <cuda_runtime.h>
#include <cuda_bf16.h>
#include <cstdint>

#define NB 4096
#define NN 8192
#define DD 128
#define MT 64
#define NT 64
#define SPAD 136   // 128 + 8 bf16 pad -> conflict-free fragment LDS

__device__ float g_znf[NN * DD];            // fp32 normalized rows
__device__ __nv_bfloat16 g_znb[NN * DD];    // bf16 normalized rows
__device__ float g_S[NN];                   // per-row sum of exp(sim - 2), diag excluded
__device__ float g_pos[NN];                 // per-row positive-pair sim (fp32)

// ---------------- kernel 1: normalize rows (one warp per row) ----------------
__global__ void __launch_bounds__(256) k_normalize(const float* __restrict__ zi,
                                                   const float* __restrict__ zj) {
    int wid = threadIdx.x >> 5, lane = threadIdx.x & 31;
    int row = blockIdx.x * 8 + wid;
    const float* src = (row < NB) ? (zi + (size_t)row * DD)
                                  : (zj + (size_t)(row - NB) * DD);
    float4 v = ((const float4*)src)[lane];
    float ss = v.x * v.x + v.y * v.y + v.z * v.z + v.w * v.w;
    #pragma unroll
    for (int o = 16; o; o >>= 1) ss += __shfl_xor_sync(0xffffffffu, ss, o);
    float norm = fmaxf(sqrtf(ss), 1e-8f);
    float rn = 1.0f / norm;
    v.x *= rn; v.y *= rn; v.z *= rn; v.w *= rn;
    ((float4*)(g_znf + (size_t)row * DD))[lane] = v;
    __nv_bfloat162 h0 = __floats2bfloat162_rn(v.x, v.y);
    __nv_bfloat162 h1 = __floats2bfloat162_rn(v.z, v.w);
    __nv_bfloat162* dst = (__nv_bfloat162*)(g_znb + (size_t)row * DD + lane * 4);
    dst[0] = h0;
    dst[1] = h1;
}

// -------- kernel 2: positive-pair similarity in fp32 (one warp per pair) -----
__global__ void __launch_bounds__(256) k_pos() {
    int wid = threadIdx.x >> 5, lane = threadIdx.x & 31;
    int i = blockIdx.x * 8 + wid;   // i in [0, NB)
    float4 a = ((const float4*)(g_znf + (size_t)i * DD))[lane];
    float4 b = ((const float4*)(g_znf + (size_t)(i + NB) * DD))[lane];
    float d = a.x * b.x + a.y * b.y + a.z * b.z + a.w * b.w;
    #pragma unroll
    for (int o = 16; o; o >>= 1) d += __shfl_xor_sync(0xffffffffu, d, o);
    if (lane == 0) {
        float s = 2.0f * d;         // / TEMP
        g_pos[i] = s;
        g_pos[i + NB] = s;
    }
}

// ---------------- bf16 tensor-core MMA m16n8k16 ------------------------------
__device__ __forceinline__ void mma_bf16(float d[4], const uint32_t a[4],
                                         uint32_t b0, uint32_t b1) {
    asm volatile(
        "mma.sync.aligned.m16n8k16.row.col.f32.bf16.bf16.f32 "
        "{%0,%1,%2,%3}, {%4,%5,%6,%7}, {%8,%9}, {%0,%1,%2,%3};\n"
        : "+f"(d[0]), "+f"(d[1]), "+f"(d[2]), "+f"(d[3])
        : "r"(a[0]), "r"(a[1]), "r"(a[2]), "r"(a[3]), "r"(b0), "r"(b1));
}

// -------- kernel 3: per-row sum of exp(sim - 2) over all columns -------------
// Grid: 128 CTAs, each owns 64 rows and streams all 8192 columns in 64-tiles.
// 8 warps as 2(m) x 4(n); warp tile = 32 rows x 16 cols.
__global__ void __launch_bounds__(256) k_simexp() {
    __shared__ __align__(16) __nv_bfloat16 As[MT * SPAD];
    __shared__ __align__(16) __nv_bfloat16 Bs[NT * SPAD];
    __shared__ float sp[MT][16];   // deterministic per-row partial reduction

    const int tid = threadIdx.x;
    const int lane = tid & 31, wid = tid >> 5;
    const int g = lane >> 2, i4 = lane & 3;
    const int wm = wid & 1, wn = wid >> 1;    // wn in 0..3
    const int m0 = blockIdx.x * MT;

    // load A rows (this CTA's 64 rows) into padded smem
    for (int c = tid; c < MT * 16; c += 256) {
        int r = c >> 4, cc = c & 15;
        *(uint4*)&As[r * SPAD + cc * 8] =
            *(const uint4*)(g_znb + (size_t)(m0 + r) * DD + cc * 8);
    }

    float acc[2][2] = {{0.f, 0.f}, {0.f, 0.f}};   // [mt][row-half]

    for (int jt = 0; jt < NN / NT; ++jt) {
        const int j0 = jt * NT;
        for (int c = tid; c < NT * 16; c += 256) {
            int r = c >> 4, cc = c & 15;
            *(uint4*)&Bs[r * SPAD + cc * 8] =
                *(const uint4*)(g_znb + (size_t)(j0 + r) * DD + cc * 8);
        }
        __syncthreads();

        float cf[2][2][4];
        #pragma unroll
        for (int mt = 0; mt < 2; ++mt)
            #pragma unroll
            for (int nt = 0; nt < 2; ++nt)
                #pragma unroll
                for (int q = 0; q < 4; ++q) cf[mt][nt][q] = 0.f;

        #pragma unroll
        for (int ks = 0; ks < 8; ++ks) {
            const int colb = ks * 16 + 2 * i4;
            uint32_t a[2][4];
            #pragma unroll
            for (int mt = 0; mt < 2; ++mt) {
                const int r0 = wm * 32 + mt * 16;
                a[mt][0] = *(const uint32_t*)&As[(r0 + g) * SPAD + colb];
                a[mt][1] = *(const uint32_t*)&As[(r0 + g + 8) * SPAD + colb];
                a[mt][2] = *(const uint32_t*)&As[(r0 + g) * SPAD + colb + 8];
                a[mt][3] = *(const uint32_t*)&As[(r0 + g + 8) * SPAD + colb + 8];
            }
            #pragma unroll
            for (int nt = 0; nt < 2; ++nt) {
                const int cb = wn * 16 + nt * 8;
                uint32_t b0 = *(const uint32_t*)&Bs[(cb + g) * SPAD + colb];
                uint32_t b1 = *(const uint32_t*)&Bs[(cb + g) * SPAD + colb + 8];
                mma_bf16(cf[0][nt], a[0], b0, b1);
                mma_bf16(cf[1][nt], a[1], b0, b1);
            }
        }

        // fused epilogue: exp(2*cos - 2), skip diagonal exactly
        #pragma unroll
        for (int mt = 0; mt < 2; ++mt) {
            const int R = m0 + wm * 32 + mt * 16 + g;
            #pragma unroll
            for (int nt = 0; nt < 2; ++nt) {
                const int C = j0 + wn * 16 + nt * 8 + 2 * i4;
                float v0 = cf[mt][nt][0], v1 = cf[mt][nt][1];
                float v2 = cf[mt][nt][2], v3 = cf[mt][nt][3];
                float e0 = (R     == C    ) ? 0.f : __expf(fmaf(2.f, v0, -2.f));
                float e1 = (R     == C + 1) ? 0.f : __expf(fmaf(2.f, v1, -2.f));
                float e2 = (R + 8 == C    ) ? 0.f : __expf(fmaf(2.f, v2, -2.f));
                float e3 = (R + 8 == C + 1) ? 0.f : __expf(fmaf(2.f, v3, -2.f));
                acc[mt][0] += e0 + e1;
                acc[mt][1] += e2 + e3;
            }
        }
        __syncthreads();   // protect Bs before next tile's load
    }

    // deterministic cross-thread reduction (no fp atomics):
    // each row is held by 16 threads: (wn in 0..3) x (i4 in 0..3)
    #pragma unroll
    for (int mt = 0; mt < 2; ++mt) {
        sp[wm * 32 + mt * 16 + g    ][wn * 4 + i4] = acc[mt][0];
        sp[wm * 32 + mt * 16 + g + 8][wn * 4 + i4] = acc[mt][1];
    }
    __syncthreads();
    if (tid < MT) {
        float s = 0.f;
        #pragma unroll
        for (int k = 0; k < 16; ++k) s += sp[tid][k];
        g_S[m0 + tid] = s;
    }
}

// ---------------- kernel 4: final scalar reduction ---------------------------
__global__ void __launch_bounds__(256) k_final(float* out) {
    __shared__ double sred[256];
    int tid = threadIdx.x;
    double t = 0.0;
    for (int i = tid; i < NN; i += 256)
        t += 2.0 + (double)logf(g_S[i]) - (double)g_pos[i];
    sred[tid] = t;
    __syncthreads();
    #pragma unroll
    for (int o = 128; o; o >>= 1) {
        if (tid < o) sred[tid] += sred[tid + o];
        __syncthreads();
    }
    if (tid == 0) out[0] = (float)(sred[0] / (double)NN);
}

extern "C" void kernel_launch(void* const* d_in, const int* in_sizes, int n_in,
                              void* d_out, int out_size) {
    const float* zi = (const float*)d_in[0];
    const float* zj = (const float*)d_in[1];
    float* out = (float*)d_out;
    (void)in_sizes; (void)n_in; (void)out_size;

    k_normalize<<<NN / 8, 256>>>(zi, zj);
    k_pos<<<NB / 8, 256>>>();
    k_simexp<<<NN / MT, 256>>>();
    k_final<<<1, 256>>>(out);
}

// round 7
// speedup vs baseline: 2.2674x; 2.2674x over previous
#include <cuda_runtime.h>
#include <cuda_bf16.h>
#include <cstdint>

#define NB 4096
#define NN 8192
#define DD 128
#define MT 64
#define NT 64
#define SPAD 136   // 128 + 8 bf16 pad (272B row stride) -> conflict-free ldmatrix

__device__ float g_znf[NN * DD];            // fp32 normalized rows
__device__ __nv_bfloat16 g_znb[NN * DD];    // bf16 normalized rows
__device__ float g_S[NN];                   // per-row sum of exp(sim - 2), diag excluded
__device__ float g_pos[NN];                 // per-row positive-pair sim (fp32)
__device__ double g_part[64];               // partial sums for final reduction

// ---------------- kernel 1: normalize rows (one warp per row) ----------------
__global__ void __launch_bounds__(256) k_normalize(const float* __restrict__ zi,
                                                   const float* __restrict__ zj) {
    int wid = threadIdx.x >> 5, lane = threadIdx.x & 31;
    int row = blockIdx.x * 8 + wid;
    const float* src = (row < NB) ? (zi + (size_t)row * DD)
                                  : (zj + (size_t)(row - NB) * DD);
    float4 v = ((const float4*)src)[lane];
    float ss = v.x * v.x + v.y * v.y + v.z * v.z + v.w * v.w;
    #pragma unroll
    for (int o = 16; o; o >>= 1) ss += __shfl_xor_sync(0xffffffffu, ss, o);
    float norm = fmaxf(sqrtf(ss), 1e-8f);
    float rn = 1.0f / norm;
    v.x *= rn; v.y *= rn; v.z *= rn; v.w *= rn;
    ((float4*)(g_znf + (size_t)row * DD))[lane] = v;
    __nv_bfloat162 h0 = __floats2bfloat162_rn(v.x, v.y);
    __nv_bfloat162 h1 = __floats2bfloat162_rn(v.z, v.w);
    __nv_bfloat162* dst = (__nv_bfloat162*)(g_znb + (size_t)row * DD + lane * 4);
    dst[0] = h0;
    dst[1] = h1;
}

// -------- kernel 2: positive-pair similarity in fp32 (one warp per pair) -----
__global__ void __launch_bounds__(256) k_pos() {
    int wid = threadIdx.x >> 5, lane = threadIdx.x & 31;
    int i = blockIdx.x * 8 + wid;   // i in [0, NB)
    float4 a = ((const float4*)(g_znf + (size_t)i * DD))[lane];
    float4 b = ((const float4*)(g_znf + (size_t)(i + NB) * DD))[lane];
    float d = a.x * b.x + a.y * b.y + a.z * b.z + a.w * b.w;
    #pragma unroll
    for (int o = 16; o; o >>= 1) d += __shfl_xor_sync(0xffffffffu, d, o);
    if (lane == 0) {
        float s = 2.0f * d;         // / TEMP
        g_pos[i] = s;
        g_pos[i + NB] = s;
    }
}

// ---------------- PTX helpers ------------------------------------------------
__device__ __forceinline__ void mma_bf16(float d[4], const uint32_t a[4],
                                         uint32_t b0, uint32_t b1) {
    asm volatile(
        "mma.sync.aligned.m16n8k16.row.col.f32.bf16.bf16.f32 "
        "{%0,%1,%2,%3}, {%4,%5,%6,%7}, {%8,%9}, {%0,%1,%2,%3};\n"
        : "+f"(d[0]), "+f"(d[1]), "+f"(d[2]), "+f"(d[3])
        : "r"(a[0]), "r"(a[1]), "r"(a[2]), "r"(a[3]), "r"(b0), "r"(b1));
}

__device__ __forceinline__ void ldmx4(uint32_t& r0, uint32_t& r1,
                                      uint32_t& r2, uint32_t& r3, uint32_t addr) {
    asm volatile("ldmatrix.sync.aligned.m8n8.x4.shared.b16 {%0,%1,%2,%3}, [%4];"
                 : "=r"(r0), "=r"(r1), "=r"(r2), "=r"(r3) : "r"(addr));
}

__device__ __forceinline__ void cp_async16(uint32_t saddr, const void* gaddr) {
    asm volatile("cp.async.ca.shared.global [%0], [%1], 16;\n"
                 :: "r"(saddr), "l"(gaddr));
}
__device__ __forceinline__ void cp_commit() {
    asm volatile("cp.async.commit_group;\n");
}
template <int N>
__device__ __forceinline__ void cp_wait() {
    asm volatile("cp.async.wait_group %0;\n" :: "n"(N));
}

// -------- kernel 3: per-row sum of exp(sim - 2) over all columns -------------
// 128 CTAs x (64 rows x all 8192 cols). A fragments register-resident,
// B via cp.async double buffer + ldmatrix.x4, fused exp epilogue.
__global__ void __launch_bounds__(256) k_simexp() {
    __shared__ __align__(16) __nv_bfloat16 As[MT * SPAD];
    __shared__ __align__(16) __nv_bfloat16 Bs[2][NT * SPAD];
    __shared__ float sp[MT][16];

    const int tid = threadIdx.x;
    const int lane = tid & 31, wid = tid >> 5;
    const int g = lane >> 2, i4 = lane & 3;
    const int wm = wid & 1, wn = wid >> 1;    // wn in 0..3
    const int m0 = blockIdx.x * MT;

    // ---- stage A rows into padded smem ----
    for (int c = tid; c < MT * 16; c += 256) {
        int r = c >> 4, cc = c & 15;
        *(uint4*)&As[r * SPAD + cc * 8] =
            *(const uint4*)(g_znb + (size_t)(m0 + r) * DD + cc * 8);
    }

    // ---- per-thread cp.async chunk assignment for B tiles (4 chunks each) ----
    uint32_t bbase[2];
    bbase[0] = (uint32_t)__cvta_generic_to_shared(&Bs[0][0]);
    bbase[1] = (uint32_t)__cvta_generic_to_shared(&Bs[1][0]);

    // prologue: prefetch tile 0 into buf 0
    {
        #pragma unroll
        for (int p = 0; p < 4; ++p) {
            int c = tid + p * 256;              // 1024 chunks total
            int r = c >> 4, cc = c & 15;
            cp_async16(bbase[0] + (uint32_t)(r * SPAD + cc * 8) * 2,
                       g_znb + (size_t)r * DD + cc * 8);
        }
        cp_commit();
    }
    __syncthreads();   // As visible

    // ---- hoist A fragments to registers: 8 ks x 2 mt x 4 regs ----
    uint32_t areg[8][2][4];
    #pragma unroll
    for (int ks = 0; ks < 8; ++ks) {
        const int colb = ks * 16 + 2 * i4;
        #pragma unroll
        for (int mt = 0; mt < 2; ++mt) {
            const int r0 = wm * 32 + mt * 16;
            areg[ks][mt][0] = *(const uint32_t*)&As[(r0 + g) * SPAD + colb];
            areg[ks][mt][1] = *(const uint32_t*)&As[(r0 + g + 8) * SPAD + colb];
            areg[ks][mt][2] = *(const uint32_t*)&As[(r0 + g) * SPAD + colb + 8];
            areg[ks][mt][3] = *(const uint32_t*)&As[(r0 + g + 8) * SPAD + colb + 8];
        }
    }

    // ldmatrix per-lane base offset (bytes) within a B buffer:
    // tiles: r0=(cb0,k0) r1=(cb0,k8) r2=(cb1,k0) r3=(cb1,k8)
    const int l8 = lane & 7;
    const int rowb = wn * 16 + ((lane >> 4) & 1) * 8 + l8;
    const int colo = ((lane >> 3) & 1) * 8;
    const uint32_t ldm_off = (uint32_t)(rowb * SPAD + colo) * 2;

    float acc[2][2] = {{0.f, 0.f}, {0.f, 0.f}};

    for (int jt = 0; jt < NN / NT; ++jt) {
        const int buf = jt & 1;
        // prefetch next tile into the other buffer (freed by last iter's end-sync)
        if (jt + 1 < NN / NT) {
            const int j1 = (jt + 1) * NT;
            #pragma unroll
            for (int p = 0; p < 4; ++p) {
                int c = tid + p * 256;
                int r = c >> 4, cc = c & 15;
                cp_async16(bbase[buf ^ 1] + (uint32_t)(r * SPAD + cc * 8) * 2,
                           g_znb + (size_t)(j1 + r) * DD + cc * 8);
            }
            cp_commit();
            cp_wait<1>();
        } else {
            cp_wait<0>();
        }
        __syncthreads();

        float cf[2][2][4];
        #pragma unroll
        for (int mt = 0; mt < 2; ++mt)
            #pragma unroll
            for (int nt = 0; nt < 2; ++nt)
                #pragma unroll
                for (int q = 0; q < 4; ++q) cf[mt][nt][q] = 0.f;

        const uint32_t bb = bbase[buf] + ldm_off;
        #pragma unroll
        for (int ks = 0; ks < 8; ++ks) {
            uint32_t b0, b1, b2, b3;
            ldmx4(b0, b1, b2, b3, bb + (uint32_t)ks * 32);
            mma_bf16(cf[0][0], areg[ks][0], b0, b1);
            mma_bf16(cf[1][0], areg[ks][1], b0, b1);
            mma_bf16(cf[0][1], areg[ks][0], b2, b3);
            mma_bf16(cf[1][1], areg[ks][1], b2, b3);
        }

        // fused epilogue: exp(2*cos - 2), skip diagonal exactly
        const int j0 = jt * NT;
        #pragma unroll
        for (int mt = 0; mt < 2; ++mt) {
            const int R = m0 + wm * 32 + mt * 16 + g;
            #pragma unroll
            for (int nt = 0; nt < 2; ++nt) {
                const int C = j0 + wn * 16 + nt * 8 + 2 * i4;
                float v0 = cf[mt][nt][0], v1 = cf[mt][nt][1];
                float v2 = cf[mt][nt][2], v3 = cf[mt][nt][3];
                float e0 = (R     == C    ) ? 0.f : __expf(fmaf(2.f, v0, -2.f));
                float e1 = (R     == C + 1) ? 0.f : __expf(fmaf(2.f, v1, -2.f));
                float e2 = (R + 8 == C    ) ? 0.f : __expf(fmaf(2.f, v2, -2.f));
                float e3 = (R + 8 == C + 1) ? 0.f : __expf(fmaf(2.f, v3, -2.f));
                acc[mt][0] += e0 + e1;
                acc[mt][1] += e2 + e3;
            }
        }
        __syncthreads();   // protect Bs[buf] before next iter prefetches into it... 
                           // (next iter writes buf^1; the iter after writes buf)
    }

    // deterministic cross-thread reduction (no fp atomics)
    #pragma unroll
    for (int mt = 0; mt < 2; ++mt) {
        sp[wm * 32 + mt * 16 + g    ][wn * 4 + i4] = acc[mt][0];
        sp[wm * 32 + mt * 16 + g + 8][wn * 4 + i4] = acc[mt][1];
    }
    __syncthreads();
    if (tid < MT) {
        float s = 0.f;
        #pragma unroll
        for (int k = 0; k < 16; ++k) s += sp[tid][k];
        g_S[m0 + tid] = s;
    }
}

// ---------------- kernel 4a: parallel partial reduction ----------------------
__global__ void __launch_bounds__(128) k_final1() {
    __shared__ double sred[128];
    int tid = threadIdx.x;
    int row = blockIdx.x * 128 + tid;
    double t = 2.0 + (double)logf(g_S[row]) - (double)g_pos[row];
    sred[tid] = t;
    __syncthreads();
    #pragma unroll
    for (int o = 64; o; o >>= 1) {
        if (tid < o) sred[tid] += sred[tid + o];
        __syncthreads();
    }
    if (tid == 0) g_part[blockIdx.x] = sred[0];
}

// ---------------- kernel 4b: final combine -----------------------------------
__global__ void __launch_bounds__(32) k_final2(float* out) {
    int tid = threadIdx.x;
    double t = g_part[tid] + g_part[tid + 32];
    #pragma unroll
    for (int o = 16; o; o >>= 1)
        t += __shfl_xor_sync(0xffffffffu, t, o);
    if (tid == 0) out[0] = (float)(t / (double)NN);
}

extern "C" void kernel_launch(void* const* d_in, const int* in_sizes, int n_in,
                              void* d_out, int out_size) {
    const float* zi = (const float*)d_in[0];
    const float* zj = (const float*)d_in[1];
    float* out = (float*)d_out;
    (void)in_sizes; (void)n_in; (void)out_size;

    k_normalize<<<NN / 8, 256>>>(zi, zj);
    k_pos<<<NB / 8, 256>>>();
    k_simexp<<<NN / MT, 256>>>();
    k_final1<<<64, 128>>>();
    k_final2<<<1, 32>>>(out);
}

// round 8
// speedup vs baseline: 3.4394x; 1.5169x over previous
#include <cuda_runtime.h>
#include <cuda_bf16.h>
#include <cstdint>

#define NB 4096
#define NN 8192
#define DD 128
#define MT 64
#define NT 64
#define HCOLS 4096   // columns per CTA (half of NN)
#define SPAD 136     // 128 + 8 bf16 pad (272B row stride) -> conflict-free ldmatrix

__device__ float g_znf[NN * DD];            // fp32 normalized rows
__device__ __nv_bfloat16 g_znb[NN * DD];    // bf16 normalized rows
__device__ float g_Sp[2][NN];               // per-row partial sums (per column half)
__device__ float g_pos[NN];                 // per-row positive-pair sim (fp32)
__device__ double g_part[64];               // partial sums for final reduction

// ---------------- kernel 1: normalize rows (one warp per row) ----------------
__global__ void __launch_bounds__(256) k_normalize(const float* __restrict__ zi,
                                                   const float* __restrict__ zj) {
    int wid = threadIdx.x >> 5, lane = threadIdx.x & 31;
    int row = blockIdx.x * 8 + wid;
    const float* src = (row < NB) ? (zi + (size_t)row * DD)
                                  : (zj + (size_t)(row - NB) * DD);
    float4 v = ((const float4*)src)[lane];
    float ss = v.x * v.x + v.y * v.y + v.z * v.z + v.w * v.w;
    #pragma unroll
    for (int o = 16; o; o >>= 1) ss += __shfl_xor_sync(0xffffffffu, ss, o);
    float norm = fmaxf(sqrtf(ss), 1e-8f);
    float rn = 1.0f / norm;
    v.x *= rn; v.y *= rn; v.z *= rn; v.w *= rn;
    ((float4*)(g_znf + (size_t)row * DD))[lane] = v;
    __nv_bfloat162 h0 = __floats2bfloat162_rn(v.x, v.y);
    __nv_bfloat162 h1 = __floats2bfloat162_rn(v.z, v.w);
    __nv_bfloat162* dst = (__nv_bfloat162*)(g_znb + (size_t)row * DD + lane * 4);
    dst[0] = h0;
    dst[1] = h1;
}

// -------- kernel 2: positive-pair similarity in fp32 (one warp per pair) -----
__global__ void __launch_bounds__(256) k_pos() {
    int wid = threadIdx.x >> 5, lane = threadIdx.x & 31;
    int i = blockIdx.x * 8 + wid;   // i in [0, NB)
    float4 a = ((const float4*)(g_znf + (size_t)i * DD))[lane];
    float4 b = ((const float4*)(g_znf + (size_t)(i + NB) * DD))[lane];
    float d = a.x * b.x + a.y * b.y + a.z * b.z + a.w * b.w;
    #pragma unroll
    for (int o = 16; o; o >>= 1) d += __shfl_xor_sync(0xffffffffu, d, o);
    if (lane == 0) {
        float s = 2.0f * d;         // / TEMP
        g_pos[i] = s;
        g_pos[i + NB] = s;
    }
}

// ---------------- PTX helpers ------------------------------------------------
__device__ __forceinline__ void mma_bf16(float d[4], const uint32_t a[4],
                                         uint32_t b0, uint32_t b1) {
    asm volatile(
        "mma.sync.aligned.m16n8k16.row.col.f32.bf16.bf16.f32 "
        "{%0,%1,%2,%3}, {%4,%5,%6,%7}, {%8,%9}, {%0,%1,%2,%3};\n"
        : "+f"(d[0]), "+f"(d[1]), "+f"(d[2]), "+f"(d[3])
        : "r"(a[0]), "r"(a[1]), "r"(a[2]), "r"(a[3]), "r"(b0), "r"(b1));
}

__device__ __forceinline__ void ldmx4(uint32_t& r0, uint32_t& r1,
                                      uint32_t& r2, uint32_t& r3, uint32_t addr) {
    asm volatile("ldmatrix.sync.aligned.m8n8.x4.shared.b16 {%0,%1,%2,%3}, [%4];"
                 : "=r"(r0), "=r"(r1), "=r"(r2), "=r"(r3) : "r"(addr));
}

__device__ __forceinline__ void cp_async16(uint32_t saddr, const void* gaddr) {
    asm volatile("cp.async.ca.shared.global [%0], [%1], 16;\n"
                 :: "r"(saddr), "l"(gaddr));
}
__device__ __forceinline__ void cp_commit() {
    asm volatile("cp.async.commit_group;\n");
}
template <int N>
__device__ __forceinline__ void cp_wait() {
    asm volatile("cp.async.wait_group %0;\n" :: "n"(N));
}

__device__ __forceinline__ float ex2f(float x) {
    float y;
    asm("ex2.approx.ftz.f32 %0, %1;" : "=f"(y) : "f"(x));
    return y;
}

// 2*log2(e): exp(2c-2) = exp2(c*C2 - C2)
#define C2 2.8853900817779268f

// -------- kernel 3: per-row partial sum of exp(sim - 2) ----------------------
// 256 CTAs: CTA (rb, half) owns 64 rows x 4096 columns. 2 CTAs/SM co-resident.
__global__ void __launch_bounds__(256, 2) k_simexp() {
    __shared__ __align__(16) __nv_bfloat16 As[MT * SPAD];
    __shared__ __align__(16) __nv_bfloat16 Bs[2][NT * SPAD];
    __shared__ float sp[MT][16];

    const int tid = threadIdx.x;
    const int lane = tid & 31, wid = tid >> 5;
    const int g = lane >> 2, i4 = lane & 3;
    const int wm = wid & 1, wn = wid >> 1;          // wn in 0..3
    const int m0 = (blockIdx.x >> 1) * MT;
    const int half = blockIdx.x & 1;
    const int c0 = half * HCOLS;

    // ---- stage A rows into padded smem ----
    for (int c = tid; c < MT * 16; c += 256) {
        int r = c >> 4, cc = c & 15;
        *(uint4*)&As[r * SPAD + cc * 8] =
            *(const uint4*)(g_znb + (size_t)(m0 + r) * DD + cc * 8);
    }

    uint32_t bbase[2];
    bbase[0] = (uint32_t)__cvta_generic_to_shared(&Bs[0][0]);
    bbase[1] = (uint32_t)__cvta_generic_to_shared(&Bs[1][0]);

    // prologue: prefetch tile 0 into buf 0
    {
        #pragma unroll
        for (int p = 0; p < 4; ++p) {
            int c = tid + p * 256;                  // 1024 chunks
            int r = c >> 4, cc = c & 15;
            cp_async16(bbase[0] + (uint32_t)(r * SPAD + cc * 8) * 2,
                       g_znb + (size_t)(c0 + r) * DD + cc * 8);
        }
        cp_commit();
    }
    __syncthreads();   // As visible

    // ---- hoist A fragments to registers ----
    uint32_t areg[8][2][4];
    #pragma unroll
    for (int ks = 0; ks < 8; ++ks) {
        const int colb = ks * 16 + 2 * i4;
        #pragma unroll
        for (int mt = 0; mt < 2; ++mt) {
            const int r0 = wm * 32 + mt * 16;
            areg[ks][mt][0] = *(const uint32_t*)&As[(r0 + g) * SPAD + colb];
            areg[ks][mt][1] = *(const uint32_t*)&As[(r0 + g + 8) * SPAD + colb];
            areg[ks][mt][2] = *(const uint32_t*)&As[(r0 + g) * SPAD + colb + 8];
            areg[ks][mt][3] = *(const uint32_t*)&As[(r0 + g + 8) * SPAD + colb + 8];
        }
    }

    const int l8 = lane & 7;
    const int rowb = wn * 16 + ((lane >> 4) & 1) * 8 + l8;
    const int colo = ((lane >> 3) & 1) * 8;
    const uint32_t ldm_off = (uint32_t)(rowb * SPAD + colo) * 2;

    float acc[2][2] = {{0.f, 0.f}, {0.f, 0.f}};

    const int NTILE = HCOLS / NT;   // 64
    for (int jt = 0; jt < NTILE; ++jt) {
        const int buf = jt & 1;
        if (jt + 1 < NTILE) {
            const int j1 = c0 + (jt + 1) * NT;
            #pragma unroll
            for (int p = 0; p < 4; ++p) {
                int c = tid + p * 256;
                int r = c >> 4, cc = c & 15;
                cp_async16(bbase[buf ^ 1] + (uint32_t)(r * SPAD + cc * 8) * 2,
                           g_znb + (size_t)(j1 + r) * DD + cc * 8);
            }
            cp_commit();
            cp_wait<1>();
        } else {
            cp_wait<0>();
        }
        __syncthreads();

        float cf[2][2][4];
        #pragma unroll
        for (int mt = 0; mt < 2; ++mt)
            #pragma unroll
            for (int nt = 0; nt < 2; ++nt)
                #pragma unroll
                for (int q = 0; q < 4; ++q) cf[mt][nt][q] = 0.f;

        const uint32_t bb = bbase[buf] + ldm_off;
        #pragma unroll
        for (int ks = 0; ks < 8; ++ks) {
            uint32_t b0, b1, b2, b3;
            ldmx4(b0, b1, b2, b3, bb + (uint32_t)ks * 32);
            mma_bf16(cf[0][0], areg[ks][0], b0, b1);
            mma_bf16(cf[1][0], areg[ks][1], b0, b1);
            mma_bf16(cf[0][1], areg[ks][0], b2, b3);
            mma_bf16(cf[1][1], areg[ks][1], b2, b3);
        }

        const int j0 = c0 + jt * NT;
        if (j0 != m0) {
            // fast path: no diagonal in this tile
            #pragma unroll
            for (int mt = 0; mt < 2; ++mt)
                #pragma unroll
                for (int nt = 0; nt < 2; ++nt) {
                    float e0 = ex2f(fmaf(cf[mt][nt][0], C2, -C2));
                    float e1 = ex2f(fmaf(cf[mt][nt][1], C2, -C2));
                    float e2 = ex2f(fmaf(cf[mt][nt][2], C2, -C2));
                    float e3 = ex2f(fmaf(cf[mt][nt][3], C2, -C2));
                    acc[mt][0] += e0 + e1;
                    acc[mt][1] += e2 + e3;
                }
        } else {
            // diagonal tile: zero out i==j terms exactly
            #pragma unroll
            for (int mt = 0; mt < 2; ++mt) {
                const int R = m0 + wm * 32 + mt * 16 + g;
                #pragma unroll
                for (int nt = 0; nt < 2; ++nt) {
                    const int C = j0 + wn * 16 + nt * 8 + 2 * i4;
                    float e0 = (R     == C    ) ? 0.f : ex2f(fmaf(cf[mt][nt][0], C2, -C2));
                    float e1 = (R     == C + 1) ? 0.f : ex2f(fmaf(cf[mt][nt][1], C2, -C2));
                    float e2 = (R + 8 == C    ) ? 0.f : ex2f(fmaf(cf[mt][nt][2], C2, -C2));
                    float e3 = (R + 8 == C + 1) ? 0.f : ex2f(fmaf(cf[mt][nt][3], C2, -C2));
                    acc[mt][0] += e0 + e1;
                    acc[mt][1] += e2 + e3;
                }
            }
        }
        __syncthreads();
    }

    // deterministic cross-thread reduction (no fp atomics)
    #pragma unroll
    for (int mt = 0; mt < 2; ++mt) {
        sp[wm * 32 + mt * 16 + g    ][wn * 4 + i4] = acc[mt][0];
        sp[wm * 32 + mt * 16 + g + 8][wn * 4 + i4] = acc[mt][1];
    }
    __syncthreads();
    if (tid < MT) {
        float s = 0.f;
        #pragma unroll
        for (int k = 0; k < 16; ++k) s += sp[tid][k];
        g_Sp[half][m0 + tid] = s;
    }
}

// ---------------- kernel 4a: parallel partial reduction ----------------------
__global__ void __launch_bounds__(128) k_final1() {
    __shared__ double sred[128];
    int tid = threadIdx.x;
    int row = blockIdx.x * 128 + tid;
    float S = g_Sp[0][row] + g_Sp[1][row];   // fixed order: deterministic
    double t = 2.0 + (double)logf(S) - (double)g_pos[row];
    sred[tid] = t;
    __syncthreads();
    #pragma unroll
    for (int o = 64; o; o >>= 1) {
        if (tid < o) sred[tid] += sred[tid + o];
        __syncthreads();
    }
    if (tid == 0) g_part[blockIdx.x] = sred[0];
}

// ---------------- kernel 4b: final combine -----------------------------------
__global__ void __launch_bounds__(32) k_final2(float* out) {
    int tid = threadIdx.x;
    double t = g_part[tid] + g_part[tid + 32];
    #pragma unroll
    for (int o = 16; o; o >>= 1)
        t += __shfl_xor_sync(0xffffffffu, t, o);
    if (tid == 0) out[0] = (float)(t / (double)NN);
}

extern "C" void kernel_launch(void* const* d_in, const int* in_sizes, int n_in,
                              void* d_out, int out_size) {
    const float* zi = (const float*)d_in[0];
    const float* zj = (const float*)d_in[1];
    float* out = (float*)d_out;
    (void)in_sizes; (void)n_in; (void)out_size;

    k_normalize<<<NN / 8, 256>>>(zi, zj);
    k_pos<<<NB / 8, 256>>>();
    k_simexp<<<NN / MT * 2, 256>>>();
    k_final1<<<64, 128>>>();
    k_final2<<<1, 32>>>(out);
}

// round 9
// speedup vs baseline: 4.4633x; 1.2977x over previous
#include <cuda_runtime.h>
#include <cuda_bf16.h>
#include <cstdint>

#define NB 4096
#define NN 8192
#define DD 128
#define MT 64
#define NT 64
#define SPAD 136     // 128 + 8 bf16 pad (272B row stride) -> conflict-free ldmatrix

__device__ float g_znf[NN * DD];            // fp32 normalized rows
__device__ __nv_bfloat16 g_znb[NN * DD];    // bf16 normalized rows
__device__ float g_Srow2[2][NN];            // register-acc row partials (per d-half)
__device__ float g_col[64][NN];             // column-sum partials, slot d-1
__device__ float g_pos[NN];                 // per-row positive-pair sim (fp32)
__device__ double g_part[64];               // partial sums for final reduction

// ---------------- kernel 1: normalize rows (one warp per row) ----------------
__global__ void __launch_bounds__(256) k_normalize(const float* __restrict__ zi,
                                                   const float* __restrict__ zj) {
    int wid = threadIdx.x >> 5, lane = threadIdx.x & 31;
    int row = blockIdx.x * 8 + wid;
    const float* src = (row < NB) ? (zi + (size_t)row * DD)
                                  : (zj + (size_t)(row - NB) * DD);
    float4 v = ((const float4*)src)[lane];
    float ss = v.x * v.x + v.y * v.y + v.z * v.z + v.w * v.w;
    #pragma unroll
    for (int o = 16; o; o >>= 1) ss += __shfl_xor_sync(0xffffffffu, ss, o);
    float norm = fmaxf(sqrtf(ss), 1e-8f);
    float rn = 1.0f / norm;
    v.x *= rn; v.y *= rn; v.z *= rn; v.w *= rn;
    ((float4*)(g_znf + (size_t)row * DD))[lane] = v;
    __nv_bfloat162 h0 = __floats2bfloat162_rn(v.x, v.y);
    __nv_bfloat162 h1 = __floats2bfloat162_rn(v.z, v.w);
    __nv_bfloat162* dst = (__nv_bfloat162*)(g_znb + (size_t)row * DD + lane * 4);
    dst[0] = h0;
    dst[1] = h1;
}

// -------- kernel 2: positive-pair similarity in fp32 (one warp per pair) -----
__global__ void __launch_bounds__(256) k_pos() {
    int wid = threadIdx.x >> 5, lane = threadIdx.x & 31;
    int i = blockIdx.x * 8 + wid;   // i in [0, NB)
    float4 a = ((const float4*)(g_znf + (size_t)i * DD))[lane];
    float4 b = ((const float4*)(g_znf + (size_t)(i + NB) * DD))[lane];
    float d = a.x * b.x + a.y * b.y + a.z * b.z + a.w * b.w;
    #pragma unroll
    for (int o = 16; o; o >>= 1) d += __shfl_xor_sync(0xffffffffu, d, o);
    if (lane == 0) {
        float s = 2.0f * d;         // / TEMP
        g_pos[i] = s;
        g_pos[i + NB] = s;
    }
}

// ---------------- PTX helpers ------------------------------------------------
__device__ __forceinline__ void mma_bf16(float d[4], const uint32_t a[4],
                                         uint32_t b0, uint32_t b1) {
    asm volatile(
        "mma.sync.aligned.m16n8k16.row.col.f32.bf16.bf16.f32 "
        "{%0,%1,%2,%3}, {%4,%5,%6,%7}, {%8,%9}, {%0,%1,%2,%3};\n"
        : "+f"(d[0]), "+f"(d[1]), "+f"(d[2]), "+f"(d[3])
        : "r"(a[0]), "r"(a[1]), "r"(a[2]), "r"(a[3]), "r"(b0), "r"(b1));
}

__device__ __forceinline__ void ldmx4(uint32_t& r0, uint32_t& r1,
                                      uint32_t& r2, uint32_t& r3, uint32_t addr) {
    asm volatile("ldmatrix.sync.aligned.m8n8.x4.shared.b16 {%0,%1,%2,%3}, [%4];"
                 : "=r"(r0), "=r"(r1), "=r"(r2), "=r"(r3) : "r"(addr));
}

__device__ __forceinline__ void cp_async16(uint32_t saddr, const void* gaddr) {
    asm volatile("cp.async.ca.shared.global [%0], [%1], 16;\n"
                 :: "r"(saddr), "l"(gaddr));
}
__device__ __forceinline__ void cp_commit() {
    asm volatile("cp.async.commit_group;\n");
}
template <int N>
__device__ __forceinline__ void cp_wait() {
    asm volatile("cp.async.wait_group %0;\n" :: "n"(N));
}

__device__ __forceinline__ float ex2f(float x) {
    float y;
    asm("ex2.approx.ftz.f32 %0, %1;" : "=f"(y) : "f"(x));
    return y;
}

// 2*log2(e): exp(2c-2) = exp2(c*C2 - C2)
#define C2 2.8853900817779268f

// -------- kernel 3: symmetric tile sweep -------------------------------------
// Unique unordered block pairs via wrapped diagonals: tile (I, (I+d)%128),
// d in [0,64] (d=64 only for I<64). Each tile's row-sums -> block I (registers),
// col-sums -> block J=(I+d)%128 (unique slot g_col[d-1]). 256 CTAs = (I, half).
__global__ void __launch_bounds__(256, 2) k_simexp() {
    __shared__ __align__(16) __nv_bfloat16 As[MT * SPAD];
    __shared__ __align__(16) __nv_bfloat16 Bs[2][NT * SPAD];
    __shared__ float sp[MT][16];
    __shared__ float scol[2][NT];

    const int tid = threadIdx.x;
    const int lane = tid & 31, wid = tid >> 5;
    const int g = lane >> 2, i4 = lane & 3;
    const int wm = wid & 1, wn = wid >> 1;          // wn in 0..3
    const int I = blockIdx.x >> 1;
    const int h = blockIdx.x & 1;
    const int m0 = I * MT;
    const int dstart = h ? 33 : 0;
    const int dend = h ? ((I < 64) ? 64 : 63) : 32;   // inclusive

    // ---- stage A rows into padded smem ----
    for (int c = tid; c < MT * 16; c += 256) {
        int r = c >> 4, cc = c & 15;
        *(uint4*)&As[r * SPAD + cc * 8] =
            *(const uint4*)(g_znb + (size_t)(m0 + r) * DD + cc * 8);
    }

    uint32_t bbase[2];
    bbase[0] = (uint32_t)__cvta_generic_to_shared(&Bs[0][0]);
    bbase[1] = (uint32_t)__cvta_generic_to_shared(&Bs[1][0]);

    // prologue: prefetch first tile into buf 0
    {
        const int j0 = ((I + dstart) & 127) * MT;
        #pragma unroll
        for (int p = 0; p < 4; ++p) {
            int c = tid + p * 256;                  // 1024 chunks
            int r = c >> 4, cc = c & 15;
            cp_async16(bbase[0] + (uint32_t)(r * SPAD + cc * 8) * 2,
                       g_znb + (size_t)(j0 + r) * DD + cc * 8);
        }
        cp_commit();
    }
    __syncthreads();   // As visible

    // ---- hoist A fragments to registers ----
    uint32_t areg[8][2][4];
    #pragma unroll
    for (int ks = 0; ks < 8; ++ks) {
        const int colb = ks * 16 + 2 * i4;
        #pragma unroll
        for (int mt = 0; mt < 2; ++mt) {
            const int r0 = wm * 32 + mt * 16;
            areg[ks][mt][0] = *(const uint32_t*)&As[(r0 + g) * SPAD + colb];
            areg[ks][mt][1] = *(const uint32_t*)&As[(r0 + g + 8) * SPAD + colb];
            areg[ks][mt][2] = *(const uint32_t*)&As[(r0 + g) * SPAD + colb + 8];
            areg[ks][mt][3] = *(const uint32_t*)&As[(r0 + g + 8) * SPAD + colb + 8];
        }
    }

    const int l8 = lane & 7;
    const int rowb = wn * 16 + ((lane >> 4) & 1) * 8 + l8;
    const int colo = ((lane >> 3) & 1) * 8;
    const uint32_t ldm_off = (uint32_t)(rowb * SPAD + colo) * 2;

    float acc[2][2] = {{0.f, 0.f}, {0.f, 0.f}};

    for (int d = dstart; d <= dend; ++d) {
        const int buf = (d - dstart) & 1;
        if (d + 1 <= dend) {
            const int j1 = ((I + d + 1) & 127) * MT;
            #pragma unroll
            for (int p = 0; p < 4; ++p) {
                int c = tid + p * 256;
                int r = c >> 4, cc = c & 15;
                cp_async16(bbase[buf ^ 1] + (uint32_t)(r * SPAD + cc * 8) * 2,
                           g_znb + (size_t)(j1 + r) * DD + cc * 8);
            }
            cp_commit();
            cp_wait<1>();
        } else {
            cp_wait<0>();
        }
        __syncthreads();   // Bs[buf] ready; prev iter's scol reads complete

        float cf[2][2][4];
        #pragma unroll
        for (int mt = 0; mt < 2; ++mt)
            #pragma unroll
            for (int nt = 0; nt < 2; ++nt)
                #pragma unroll
                for (int q = 0; q < 4; ++q) cf[mt][nt][q] = 0.f;

        const uint32_t bb = bbase[buf] + ldm_off;
        #pragma unroll
        for (int ks = 0; ks < 8; ++ks) {
            uint32_t b0, b1, b2, b3;
            ldmx4(b0, b1, b2, b3, bb + (uint32_t)ks * 32);
            mma_bf16(cf[0][0], areg[ks][0], b0, b1);
            mma_bf16(cf[1][0], areg[ks][1], b0, b1);
            mma_bf16(cf[0][1], areg[ks][0], b2, b3);
            mma_bf16(cf[1][1], areg[ks][1], b2, b3);
        }

        const int j0 = ((I + d) & 127) * MT;
        if (d != 0) {
            // off-diagonal tile: exp + row acc + column partial sums
            float cs0[2] = {0.f, 0.f}, cs1[2] = {0.f, 0.f};
            #pragma unroll
            for (int mt = 0; mt < 2; ++mt)
                #pragma unroll
                for (int nt = 0; nt < 2; ++nt) {
                    float e0 = ex2f(fmaf(cf[mt][nt][0], C2, -C2));
                    float e1 = ex2f(fmaf(cf[mt][nt][1], C2, -C2));
                    float e2 = ex2f(fmaf(cf[mt][nt][2], C2, -C2));
                    float e3 = ex2f(fmaf(cf[mt][nt][3], C2, -C2));
                    acc[mt][0] += e0 + e1;
                    acc[mt][1] += e2 + e3;
                    cs0[nt] += e0 + e2;
                    cs1[nt] += e1 + e3;
                }
            // reduce column partials over g (lanes stride 4)
            #pragma unroll
            for (int nt = 0; nt < 2; ++nt) {
                #pragma unroll
                for (int o = 4; o <= 16; o <<= 1) {
                    cs0[nt] += __shfl_xor_sync(0xffffffffu, cs0[nt], o);
                    cs1[nt] += __shfl_xor_sync(0xffffffffu, cs1[nt], o);
                }
            }
            if (g == 0) {   // lanes 0..3, i4 == lane
                #pragma unroll
                for (int nt = 0; nt < 2; ++nt) {
                    scol[wm][wn * 16 + nt * 8 + 2 * lane    ] = cs0[nt];
                    scol[wm][wn * 16 + nt * 8 + 2 * lane + 1] = cs1[nt];
                }
            }
            __syncthreads();   // scol visible; Bs[buf] reads complete
            if (tid < NT)
                g_col[d - 1][j0 + tid] = scol[0][tid] + scol[1][tid];
        } else {
            // diagonal tile: row sums only, mask i==j exactly
            #pragma unroll
            for (int mt = 0; mt < 2; ++mt) {
                const int R = m0 + wm * 32 + mt * 16 + g;
                #pragma unroll
                for (int nt = 0; nt < 2; ++nt) {
                    const int C = j0 + wn * 16 + nt * 8 + 2 * i4;
                    float e0 = (R     == C    ) ? 0.f : ex2f(fmaf(cf[mt][nt][0], C2, -C2));
                    float e1 = (R     == C + 1) ? 0.f : ex2f(fmaf(cf[mt][nt][1], C2, -C2));
                    float e2 = (R + 8 == C    ) ? 0.f : ex2f(fmaf(cf[mt][nt][2], C2, -C2));
                    float e3 = (R + 8 == C + 1) ? 0.f : ex2f(fmaf(cf[mt][nt][3], C2, -C2));
                    acc[mt][0] += e0 + e1;
                    acc[mt][1] += e2 + e3;
                }
            }
            __syncthreads();   // Bs[buf] reads complete before next prefetch
        }
    }

    // deterministic cross-thread reduction of register row partials
    #pragma unroll
    for (int mt = 0; mt < 2; ++mt) {
        sp[wm * 32 + mt * 16 + g    ][wn * 4 + i4] = acc[mt][0];
        sp[wm * 32 + mt * 16 + g + 8][wn * 4 + i4] = acc[mt][1];
    }
    __syncthreads();
    if (tid < MT) {
        float s = 0.f;
        #pragma unroll
        for (int k = 0; k < 16; ++k) s += sp[tid][k];
        g_Srow2[h][m0 + tid] = s;
    }
}

// ---------------- kernel 4a: assemble row sums + partial reduction -----------
__global__ void __launch_bounds__(128) k_final1() {
    __shared__ double sred[128];
    int tid = threadIdx.x;
    int row = blockIdx.x * 128 + tid;
    float S = g_Srow2[0][row] + g_Srow2[1][row];
    #pragma unroll 9
    for (int d = 0; d < 63; ++d) S += g_col[d][row];
    if (row >= NB) S += g_col[63][row];     // d=64 slot exists only for 2nd half
    double t = 2.0 + (double)logf(S) - (double)g_pos[row];
    sred[tid] = t;
    __syncthreads();
    #pragma unroll
    for (int o = 64; o; o >>= 1) {
        if (tid < o) sred[tid] += sred[tid + o];
        __syncthreads();
    }
    if (tid == 0) g_part[blockIdx.x] = sred[0];
}

// ---------------- kernel 4b: final combine -----------------------------------
__global__ void __launch_bounds__(32) k_final2(float* out) {
    int tid = threadIdx.x;
    double t = g_part[tid] + g_part[tid + 32];
    #pragma unroll
    for (int o = 16; o; o >>= 1)
        t += __shfl_xor_sync(0xffffffffu, t, o);
    if (tid == 0) out[0] = (float)(t / (double)NN);
}

extern "C" void kernel_launch(void* const* d_in, const int* in_sizes, int n_in,
                              void* d_out, int out_size) {
    const float* zi = (const float*)d_in[0];
    const float* zj = (const float*)d_in[1];
    float* out = (float*)d_out;
    (void)in_sizes; (void)n_in; (void)out_size;

    k_normalize<<<NN / 8, 256>>>(zi, zj);
    k_pos<<<NB / 8, 256>>>();
    k_simexp<<<256, 256>>>();
    k_final1<<<64, 128>>>();
    k_final2<<<1, 32>>>(out);
}

// round 10
// speedup vs baseline: 4.8004x; 1.0755x over previous
#include <cuda_runtime.h>
#include <cuda_bf16.h>
#include <cstdint>

#define NB 4096
#define NN 8192
#define DD 128
#define MT 64
#define NT 64
#define SPAD 136     // 128 + 8 bf16 pad (272B row stride) -> conflict-free ldmatrix

__device__ float g_znf[NN * DD];            // fp32 normalized rows
__device__ __nv_bfloat16 g_znb[NN * DD];    // bf16 normalized rows
__device__ float g_Srow2[2][NN];            // register-acc row partials (per d-half)
__device__ float g_colh[2][64][NN];         // column-sum partials [wm][d-1][col]
__device__ float g_pos[NN];                 // per-row positive-pair sim (fp32)
__device__ double g_part[128];              // partial sums for final reduction

// ---------------- kernel 1: normalize rows (one warp per row) ----------------
__global__ void __launch_bounds__(256) k_normalize(const float* __restrict__ zi,
                                                   const float* __restrict__ zj) {
    int wid = threadIdx.x >> 5, lane = threadIdx.x & 31;
    int row = blockIdx.x * 8 + wid;
    const float* src = (row < NB) ? (zi + (size_t)row * DD)
                                  : (zj + (size_t)(row - NB) * DD);
    float4 v = ((const float4*)src)[lane];
    float ss = v.x * v.x + v.y * v.y + v.z * v.z + v.w * v.w;
    #pragma unroll
    for (int o = 16; o; o >>= 1) ss += __shfl_xor_sync(0xffffffffu, ss, o);
    float norm = fmaxf(sqrtf(ss), 1e-8f);
    float rn = 1.0f / norm;
    v.x *= rn; v.y *= rn; v.z *= rn; v.w *= rn;
    ((float4*)(g_znf + (size_t)row * DD))[lane] = v;
    __nv_bfloat162 h0 = __floats2bfloat162_rn(v.x, v.y);
    __nv_bfloat162 h1 = __floats2bfloat162_rn(v.z, v.w);
    __nv_bfloat162* dst = (__nv_bfloat162*)(g_znb + (size_t)row * DD + lane * 4);
    dst[0] = h0;
    dst[1] = h1;
}

// -------- kernel 2: positive-pair similarity in fp32 (one warp per pair) -----
__global__ void __launch_bounds__(256) k_pos() {
    int wid = threadIdx.x >> 5, lane = threadIdx.x & 31;
    int i = blockIdx.x * 8 + wid;   // i in [0, NB)
    float4 a = ((const float4*)(g_znf + (size_t)i * DD))[lane];
    float4 b = ((const float4*)(g_znf + (size_t)(i + NB) * DD))[lane];
    float d = a.x * b.x + a.y * b.y + a.z * b.z + a.w * b.w;
    #pragma unroll
    for (int o = 16; o; o >>= 1) d += __shfl_xor_sync(0xffffffffu, d, o);
    if (lane == 0) {
        float s = 2.0f * d;         // / TEMP
        g_pos[i] = s;
        g_pos[i + NB] = s;
    }
}

// ---------------- PTX helpers ------------------------------------------------
__device__ __forceinline__ void mma_bf16(float d[4], const uint32_t a[4],
                                         uint32_t b0, uint32_t b1) {
    asm volatile(
        "mma.sync.aligned.m16n8k16.row.col.f32.bf16.bf16.f32 "
        "{%0,%1,%2,%3}, {%4,%5,%6,%7}, {%8,%9}, {%0,%1,%2,%3};\n"
        : "+f"(d[0]), "+f"(d[1]), "+f"(d[2]), "+f"(d[3])
        : "r"(a[0]), "r"(a[1]), "r"(a[2]), "r"(a[3]), "r"(b0), "r"(b1));
}

__device__ __forceinline__ void ldmx4(uint32_t& r0, uint32_t& r1,
                                      uint32_t& r2, uint32_t& r3, uint32_t addr) {
    asm volatile("ldmatrix.sync.aligned.m8n8.x4.shared.b16 {%0,%1,%2,%3}, [%4];"
                 : "=r"(r0), "=r"(r1), "=r"(r2), "=r"(r3) : "r"(addr));
}

__device__ __forceinline__ void cp_async16(uint32_t saddr, const void* gaddr) {
    asm volatile("cp.async.ca.shared.global [%0], [%1], 16;\n"
                 :: "r"(saddr), "l"(gaddr));
}
__device__ __forceinline__ void cp_commit() {
    asm volatile("cp.async.commit_group;\n");
}
template <int N>
__device__ __forceinline__ void cp_wait() {
    asm volatile("cp.async.wait_group %0;\n" :: "n"(N));
}

__device__ __forceinline__ float ex2f(float x) {
    float y;
    asm("ex2.approx.ftz.f32 %0, %1;" : "=f"(y) : "f"(x));
    return y;
}

// 2*log2(e): exp(2c-2) = exp2(c*C2 - C2)
#define C2 2.8853900817779268f

// -------- kernel 3: symmetric tile sweep -------------------------------------
// Unique unordered block pairs via wrapped diagonals: tile (I, (I+d)%128),
// d in [0,64] (d=64 only for I<64). Row-sums -> block I (registers),
// col-sums -> block J=(I+d)%128, stored per-warp-row-half into unique slots
// g_colh[wm][d-1][col] (float2, no barrier). 256 CTAs = (I, half).
__global__ void __launch_bounds__(256, 2) k_simexp() {
    __shared__ __align__(16) __nv_bfloat16 As[MT * SPAD];
    __shared__ __align__(16) __nv_bfloat16 Bs[2][NT * SPAD];
    __shared__ float sp[MT][16];

    const int tid = threadIdx.x;
    const int lane = tid & 31, wid = tid >> 5;
    const int g = lane >> 2, i4 = lane & 3;
    const int wm = wid & 1, wn = wid >> 1;          // wn in 0..3
    const int I = blockIdx.x >> 1;
    const int h = blockIdx.x & 1;
    const int m0 = I * MT;
    const int dstart = h ? 33 : 0;
    const int dend = h ? ((I < 64) ? 64 : 63) : 32;   // inclusive

    // ---- stage A rows into padded smem ----
    for (int c = tid; c < MT * 16; c += 256) {
        int r = c >> 4, cc = c & 15;
        *(uint4*)&As[r * SPAD + cc * 8] =
            *(const uint4*)(g_znb + (size_t)(m0 + r) * DD + cc * 8);
    }

    uint32_t bbase[2];
    bbase[0] = (uint32_t)__cvta_generic_to_shared(&Bs[0][0]);
    bbase[1] = (uint32_t)__cvta_generic_to_shared(&Bs[1][0]);

    // prologue: prefetch first tile into buf 0
    {
        const int j0 = ((I + dstart) & 127) * MT;
        #pragma unroll
        for (int p = 0; p < 4; ++p) {
            int c = tid + p * 256;                  // 1024 chunks
            int r = c >> 4, cc = c & 15;
            cp_async16(bbase[0] + (uint32_t)(r * SPAD + cc * 8) * 2,
                       g_znb + (size_t)(j0 + r) * DD + cc * 8);
        }
        cp_commit();
    }
    __syncthreads();   // As visible

    // ---- hoist A fragments to registers ----
    uint32_t areg[8][2][4];
    #pragma unroll
    for (int ks = 0; ks < 8; ++ks) {
        const int colb = ks * 16 + 2 * i4;
        #pragma unroll
        for (int mt = 0; mt < 2; ++mt) {
            const int r0 = wm * 32 + mt * 16;
            areg[ks][mt][0] = *(const uint32_t*)&As[(r0 + g) * SPAD + colb];
            areg[ks][mt][1] = *(const uint32_t*)&As[(r0 + g + 8) * SPAD + colb];
            areg[ks][mt][2] = *(const uint32_t*)&As[(r0 + g) * SPAD + colb + 8];
            areg[ks][mt][3] = *(const uint32_t*)&As[(r0 + g + 8) * SPAD + colb + 8];
        }
    }

    const int l8 = lane & 7;
    const int rowb = wn * 16 + ((lane >> 4) & 1) * 8 + l8;
    const int colo = ((lane >> 3) & 1) * 8;
    const uint32_t ldm_off = (uint32_t)(rowb * SPAD + colo) * 2;

    float acc[2][2] = {{0.f, 0.f}, {0.f, 0.f}};

    for (int d = dstart; d <= dend; ++d) {
        const int buf = (d - dstart) & 1;
        // publish buf (cp group done for everyone after barrier) AND
        // guarantee all warps finished reading buf^1 from last iteration
        cp_wait<0>();
        __syncthreads();

        // issue next prefetch immediately; it overlaps this tile's compute
        if (d + 1 <= dend) {
            const int j1 = ((I + d + 1) & 127) * MT;
            #pragma unroll
            for (int p = 0; p < 4; ++p) {
                int c = tid + p * 256;
                int r = c >> 4, cc = c & 15;
                cp_async16(bbase[buf ^ 1] + (uint32_t)(r * SPAD + cc * 8) * 2,
                           g_znb + (size_t)(j1 + r) * DD + cc * 8);
            }
            cp_commit();
        }

        float cf[2][2][4];
        #pragma unroll
        for (int mt = 0; mt < 2; ++mt)
            #pragma unroll
            for (int nt = 0; nt < 2; ++nt)
                #pragma unroll
                for (int q = 0; q < 4; ++q) cf[mt][nt][q] = 0.f;

        const uint32_t bb = bbase[buf] + ldm_off;
        #pragma unroll
        for (int ks = 0; ks < 8; ++ks) {
            uint32_t b0, b1, b2, b3;
            ldmx4(b0, b1, b2, b3, bb + (uint32_t)ks * 32);
            mma_bf16(cf[0][0], areg[ks][0], b0, b1);
            mma_bf16(cf[1][0], areg[ks][1], b0, b1);
            mma_bf16(cf[0][1], areg[ks][0], b2, b3);
            mma_bf16(cf[1][1], areg[ks][1], b2, b3);
        }

        const int j0 = ((I + d) & 127) * MT;
        if (d != 0) {
            // off-diagonal tile: exp + row acc + column partial sums
            float cs0[2] = {0.f, 0.f}, cs1[2] = {0.f, 0.f};
            #pragma unroll
            for (int mt = 0; mt < 2; ++mt)
                #pragma unroll
                for (int nt = 0; nt < 2; ++nt) {
                    float e0 = ex2f(fmaf(cf[mt][nt][0], C2, -C2));
                    float e1 = ex2f(fmaf(cf[mt][nt][1], C2, -C2));
                    float e2 = ex2f(fmaf(cf[mt][nt][2], C2, -C2));
                    float e3 = ex2f(fmaf(cf[mt][nt][3], C2, -C2));
                    acc[mt][0] += e0 + e1;
                    acc[mt][1] += e2 + e3;
                    cs0[nt] += e0 + e2;
                    cs1[nt] += e1 + e3;
                }
            // reduce column partials over g (lanes stride 4)
            #pragma unroll
            for (int nt = 0; nt < 2; ++nt) {
                #pragma unroll
                for (int o = 4; o <= 16; o <<= 1) {
                    cs0[nt] += __shfl_xor_sync(0xffffffffu, cs0[nt], o);
                    cs1[nt] += __shfl_xor_sync(0xffffffffu, cs1[nt], o);
                }
            }
            if (g == 0) {   // lanes 0..3 hold totals; direct float2 store, no barrier
                #pragma unroll
                for (int nt = 0; nt < 2; ++nt) {
                    const int C = wn * 16 + nt * 8 + 2 * i4;
                    float2 v = make_float2(cs0[nt], cs1[nt]);
                    *(float2*)&g_colh[wm][d - 1][j0 + C] = v;
                }
            }
        } else {
            // diagonal tile: row sums only, mask i==j exactly
            #pragma unroll
            for (int mt = 0; mt < 2; ++mt) {
                const int R = m0 + wm * 32 + mt * 16 + g;
                #pragma unroll
                for (int nt = 0; nt < 2; ++nt) {
                    const int C = j0 + wn * 16 + nt * 8 + 2 * i4;
                    float e0 = (R     == C    ) ? 0.f : ex2f(fmaf(cf[mt][nt][0], C2, -C2));
                    float e1 = (R     == C + 1) ? 0.f : ex2f(fmaf(cf[mt][nt][1], C2, -C2));
                    float e2 = (R + 8 == C    ) ? 0.f : ex2f(fmaf(cf[mt][nt][2], C2, -C2));
                    float e3 = (R + 8 == C + 1) ? 0.f : ex2f(fmaf(cf[mt][nt][3], C2, -C2));
                    acc[mt][0] += e0 + e1;
                    acc[mt][1] += e2 + e3;
                }
            }
        }
    }

    // deterministic cross-thread reduction of register row partials
    __syncthreads();
    #pragma unroll
    for (int mt = 0; mt < 2; ++mt) {
        sp[wm * 32 + mt * 16 + g    ][wn * 4 + i4] = acc[mt][0];
        sp[wm * 32 + mt * 16 + g + 8][wn * 4 + i4] = acc[mt][1];
    }
    __syncthreads();
    if (tid < MT) {
        float s = 0.f;
        #pragma unroll
        for (int k = 0; k < 16; ++k) s += sp[tid][k];
        g_Srow2[h][m0 + tid] = s;
    }
}

// ---------------- kernel 4a: assemble row sums + partial reduction -----------
// 128 blocks x 256 threads; 64 rows/block; 4 thread-groups split the d-range.
__global__ void __launch_bounds__(256) k_final1() {
    __shared__ float sredf[4][64];
    __shared__ double sd[64];
    const int tid = threadIdx.x;
    const int q = tid >> 6;          // 0..3 (d-range quarter)
    const int r = tid & 63;          // row within block
    const int row = blockIdx.x * 64 + r;

    float s = 0.f;
    if (q == 0) s = g_Srow2[0][row] + g_Srow2[1][row];
    const int d0 = q * 16;
    const int d1 = (q == 3) ? 63 : (d0 + 16);
    for (int d = d0; d < d1; ++d)
        s += g_colh[0][d][row] + g_colh[1][d][row];
    if (q == 3 && row >= NB)
        s += g_colh[0][63][row] + g_colh[1][63][row];
    sredf[q][r] = s;
    __syncthreads();

    if (tid < 64) {
        float S = sredf[0][tid] + sredf[1][tid] + sredf[2][tid] + sredf[3][tid];
        int rw = blockIdx.x * 64 + tid;
        sd[tid] = 2.0 + (double)logf(S) - (double)g_pos[rw];
    }
    __syncthreads();
    if (tid < 32) {
        double t = sd[tid] + sd[tid + 32];
        #pragma unroll
        for (int o = 16; o; o >>= 1)
            t += __shfl_xor_sync(0xffffffffu, t, o);
        if (tid == 0) g_part[blockIdx.x] = t;
    }
}

// ---------------- kernel 4b: final combine -----------------------------------
__global__ void __launch_bounds__(32) k_final2(float* out) {
    int tid = threadIdx.x;
    double t = g_part[tid] + g_part[tid + 32] + g_part[tid + 64] + g_part[tid + 96];
    #pragma unroll
    for (int o = 16; o; o >>= 1)
        t += __shfl_xor_sync(0xffffffffu, t, o);
    if (tid == 0) out[0] = (float)(t / (double)NN);
}

extern "C" void kernel_launch(void* const* d_in, const int* in_sizes, int n_in,
                              void* d_out, int out_size) {
    const float* zi = (const float*)d_in[0];
    const float* zj = (const float*)d_in[1];
    float* out = (float*)d_out;
    (void)in_sizes; (void)n_in; (void)out_size;

    k_normalize<<<NN / 8, 256>>>(zi, zj);
    k_pos<<<NB / 8, 256>>>();
    k_simexp<<<256, 256>>>();
    k_final1<<<128, 256>>>();
    k_final2<<<1, 32>>>(out);
}

// round 11
// speedup vs baseline: 4.9093x; 1.0227x over previous
#include <cuda_runtime.h>
#include <cuda_bf16.h>
#include <cstdint>

#define NB 4096
#define NN 8192
#define DD 128
#define MT 64
#define NT 64
#define SPAD 136     // 128 + 8 bf16 pad (272B row stride) -> conflict-free ldmatrix

__device__ __nv_bfloat16 g_znb[NN * DD];    // bf16 normalized rows
__device__ float g_Srow2[2][NN];            // register-acc row partials (per d-half)
__device__ float g_colh[2][64][NN];         // column-sum partials [wm][d-1][col]
__device__ float g_pos[NN];                 // per-row positive-pair sim (fp32)
__device__ double g_part[256];              // partial sums for final reduction

// ---------------- kernel 1: normalize rows (one warp per row) ----------------
__global__ void __launch_bounds__(256) k_normalize(const float* __restrict__ zi,
                                                   const float* __restrict__ zj) {
    int wid = threadIdx.x >> 5, lane = threadIdx.x & 31;
    int row = blockIdx.x * 8 + wid;
    const float* src = (row < NB) ? (zi + (size_t)row * DD)
                                  : (zj + (size_t)(row - NB) * DD);
    float4 v = ((const float4*)src)[lane];
    float ss = v.x * v.x + v.y * v.y + v.z * v.z + v.w * v.w;
    #pragma unroll
    for (int o = 16; o; o >>= 1) ss += __shfl_xor_sync(0xffffffffu, ss, o);
    float norm = fmaxf(sqrtf(ss), 1e-8f);
    float rn = 1.0f / norm;
    v.x *= rn; v.y *= rn; v.z *= rn; v.w *= rn;
    __nv_bfloat162 h0 = __floats2bfloat162_rn(v.x, v.y);
    __nv_bfloat162 h1 = __floats2bfloat162_rn(v.z, v.w);
    __nv_bfloat162* dst = (__nv_bfloat162*)(g_znb + (size_t)row * DD + lane * 4);
    dst[0] = h0;
    dst[1] = h1;
}

// -------- kernel 2: positive-pair similarity straight from raw inputs --------
// one warp per pair; dot + both norms in one pass (no g_znf dependency)
__global__ void __launch_bounds__(256) k_pos(const float* __restrict__ zi,
                                             const float* __restrict__ zj) {
    int wid = threadIdx.x >> 5, lane = threadIdx.x & 31;
    int i = blockIdx.x * 8 + wid;   // i in [0, NB)
    float4 a = ((const float4*)(zi + (size_t)i * DD))[lane];
    float4 b = ((const float4*)(zj + (size_t)i * DD))[lane];
    float d  = a.x * b.x + a.y * b.y + a.z * b.z + a.w * b.w;
    float na = a.x * a.x + a.y * a.y + a.z * a.z + a.w * a.w;
    float nb = b.x * b.x + b.y * b.y + b.z * b.z + b.w * b.w;
    #pragma unroll
    for (int o = 16; o; o >>= 1) {
        d  += __shfl_xor_sync(0xffffffffu, d, o);
        na += __shfl_xor_sync(0xffffffffu, na, o);
        nb += __shfl_xor_sync(0xffffffffu, nb, o);
    }
    if (lane == 0) {
        float inv = 1.0f / (fmaxf(sqrtf(na), 1e-8f) * fmaxf(sqrtf(nb), 1e-8f));
        float s = 2.0f * d * inv;   // / TEMP
        g_pos[i] = s;
        g_pos[i + NB] = s;
    }
}

// ---------------- PTX helpers ------------------------------------------------
__device__ __forceinline__ void mma_bf16(float d[4], const uint32_t a[4],
                                         uint32_t b0, uint32_t b1) {
    asm volatile(
        "mma.sync.aligned.m16n8k16.row.col.f32.bf16.bf16.f32 "
        "{%0,%1,%2,%3}, {%4,%5,%6,%7}, {%8,%9}, {%0,%1,%2,%3};\n"
        : "+f"(d[0]), "+f"(d[1]), "+f"(d[2]), "+f"(d[3])
        : "r"(a[0]), "r"(a[1]), "r"(a[2]), "r"(a[3]), "r"(b0), "r"(b1));
}

__device__ __forceinline__ void ldmx4(uint32_t& r0, uint32_t& r1,
                                      uint32_t& r2, uint32_t& r3, uint32_t addr) {
    asm volatile("ldmatrix.sync.aligned.m8n8.x4.shared.b16 {%0,%1,%2,%3}, [%4];"
                 : "=r"(r0), "=r"(r1), "=r"(r2), "=r"(r3) : "r"(addr));
}

__device__ __forceinline__ void cp_async16(uint32_t saddr, const void* gaddr) {
    asm volatile("cp.async.ca.shared.global [%0], [%1], 16;\n"
                 :: "r"(saddr), "l"(gaddr));
}
__device__ __forceinline__ void cp_commit() {
    asm volatile("cp.async.commit_group;\n");
}
template <int N>
__device__ __forceinline__ void cp_wait() {
    asm volatile("cp.async.wait_group %0;\n" :: "n"(N));
}

__device__ __forceinline__ float ex2f(float x) {
    float y;
    asm("ex2.approx.ftz.f32 %0, %1;" : "=f"(y) : "f"(x));
    return y;
}

// 2*log2(e): exp(2c-2) = exp2(c*C2 - C2)
#define C2 2.8853900817779268f

// -------- kernel 3: symmetric tile sweep (unchanged from R10) ----------------
__global__ void __launch_bounds__(256, 2) k_simexp() {
    __shared__ __align__(16) __nv_bfloat16 As[MT * SPAD];
    __shared__ __align__(16) __nv_bfloat16 Bs[2][NT * SPAD];
    __shared__ float sp[MT][16];

    const int tid = threadIdx.x;
    const int lane = tid & 31, wid = tid >> 5;
    const int g = lane >> 2, i4 = lane & 3;
    const int wm = wid & 1, wn = wid >> 1;          // wn in 0..3
    const int I = blockIdx.x >> 1;
    const int h = blockIdx.x & 1;
    const int m0 = I * MT;
    const int dstart = h ? 33 : 0;
    const int dend = h ? ((I < 64) ? 64 : 63) : 32;   // inclusive

    for (int c = tid; c < MT * 16; c += 256) {
        int r = c >> 4, cc = c & 15;
        *(uint4*)&As[r * SPAD + cc * 8] =
            *(const uint4*)(g_znb + (size_t)(m0 + r) * DD + cc * 8);
    }

    uint32_t bbase[2];
    bbase[0] = (uint32_t)__cvta_generic_to_shared(&Bs[0][0]);
    bbase[1] = (uint32_t)__cvta_generic_to_shared(&Bs[1][0]);

    {
        const int j0 = ((I + dstart) & 127) * MT;
        #pragma unroll
        for (int p = 0; p < 4; ++p) {
            int c = tid + p * 256;                  // 1024 chunks
            int r = c >> 4, cc = c & 15;
            cp_async16(bbase[0] + (uint32_t)(r * SPAD + cc * 8) * 2,
                       g_znb + (size_t)(j0 + r) * DD + cc * 8);
        }
        cp_commit();
    }
    __syncthreads();   // As visible

    uint32_t areg[8][2][4];
    #pragma unroll
    for (int ks = 0; ks < 8; ++ks) {
        const int colb = ks * 16 + 2 * i4;
        #pragma unroll
        for (int mt = 0; mt < 2; ++mt) {
            const int r0 = wm * 32 + mt * 16;
            areg[ks][mt][0] = *(const uint32_t*)&As[(r0 + g) * SPAD + colb];
            areg[ks][mt][1] = *(const uint32_t*)&As[(r0 + g + 8) * SPAD + colb];
            areg[ks][mt][2] = *(const uint32_t*)&As[(r0 + g) * SPAD + colb + 8];
            areg[ks][mt][3] = *(const uint32_t*)&As[(r0 + g + 8) * SPAD + colb + 8];
        }
    }

    const int l8 = lane & 7;
    const int rowb = wn * 16 + ((lane >> 4) & 1) * 8 + l8;
    const int colo = ((lane >> 3) & 1) * 8;
    const uint32_t ldm_off = (uint32_t)(rowb * SPAD + colo) * 2;

    float acc[2][2] = {{0.f, 0.f}, {0.f, 0.f}};

    for (int d = dstart; d <= dend; ++d) {
        const int buf = (d - dstart) & 1;
        cp_wait<0>();
        __syncthreads();

        if (d + 1 <= dend) {
            const int j1 = ((I + d + 1) & 127) * MT;
            #pragma unroll
            for (int p = 0; p < 4; ++p) {
                int c = tid + p * 256;
                int r = c >> 4, cc = c & 15;
                cp_async16(bbase[buf ^ 1] + (uint32_t)(r * SPAD + cc * 8) * 2,
                           g_znb + (size_t)(j1 + r) * DD + cc * 8);
            }
            cp_commit();
        }

        float cf[2][2][4];
        #pragma unroll
        for (int mt = 0; mt < 2; ++mt)
            #pragma unroll
            for (int nt = 0; nt < 2; ++nt)
                #pragma unroll
                for (int q = 0; q < 4; ++q) cf[mt][nt][q] = 0.f;

        const uint32_t bb = bbase[buf] + ldm_off;
        #pragma unroll
        for (int ks = 0; ks < 8; ++ks) {
            uint32_t b0, b1, b2, b3;
            ldmx4(b0, b1, b2, b3, bb + (uint32_t)ks * 32);
            mma_bf16(cf[0][0], areg[ks][0], b0, b1);
            mma_bf16(cf[1][0], areg[ks][1], b0, b1);
            mma_bf16(cf[0][1], areg[ks][0], b2, b3);
            mma_bf16(cf[1][1], areg[ks][1], b2, b3);
        }

        const int j0 = ((I + d) & 127) * MT;
        if (d != 0) {
            float cs0[2] = {0.f, 0.f}, cs1[2] = {0.f, 0.f};
            #pragma unroll
            for (int mt = 0; mt < 2; ++mt)
                #pragma unroll
                for (int nt = 0; nt < 2; ++nt) {
                    float e0 = ex2f(fmaf(cf[mt][nt][0], C2, -C2));
                    float e1 = ex2f(fmaf(cf[mt][nt][1], C2, -C2));
                    float e2 = ex2f(fmaf(cf[mt][nt][2], C2, -C2));
                    float e3 = ex2f(fmaf(cf[mt][nt][3], C2, -C2));
                    acc[mt][0] += e0 + e1;
                    acc[mt][1] += e2 + e3;
                    cs0[nt] += e0 + e2;
                    cs1[nt] += e1 + e3;
                }
            #pragma unroll
            for (int nt = 0; nt < 2; ++nt) {
                #pragma unroll
                for (int o = 4; o <= 16; o <<= 1) {
                    cs0[nt] += __shfl_xor_sync(0xffffffffu, cs0[nt], o);
                    cs1[nt] += __shfl_xor_sync(0xffffffffu, cs1[nt], o);
                }
            }
            if (g == 0) {
                #pragma unroll
                for (int nt = 0; nt < 2; ++nt) {
                    const int C = wn * 16 + nt * 8 + 2 * i4;
                    float2 v = make_float2(cs0[nt], cs1[nt]);
                    *(float2*)&g_colh[wm][d - 1][j0 + C] = v;
                }
            }
        } else {
            #pragma unroll
            for (int mt = 0; mt < 2; ++mt) {
                const int R = m0 + wm * 32 + mt * 16 + g;
                #pragma unroll
                for (int nt = 0; nt < 2; ++nt) {
                    const int C = j0 + wn * 16 + nt * 8 + 2 * i4;
                    float e0 = (R     == C    ) ? 0.f : ex2f(fmaf(cf[mt][nt][0], C2, -C2));
                    float e1 = (R     == C + 1) ? 0.f : ex2f(fmaf(cf[mt][nt][1], C2, -C2));
                    float e2 = (R + 8 == C    ) ? 0.f : ex2f(fmaf(cf[mt][nt][2], C2, -C2));
                    float e3 = (R + 8 == C + 1) ? 0.f : ex2f(fmaf(cf[mt][nt][3], C2, -C2));
                    acc[mt][0] += e0 + e1;
                    acc[mt][1] += e2 + e3;
                }
            }
        }
    }

    __syncthreads();
    #pragma unroll
    for (int mt = 0; mt < 2; ++mt) {
        sp[wm * 32 + mt * 16 + g    ][wn * 4 + i4] = acc[mt][0];
        sp[wm * 32 + mt * 16 + g + 8][wn * 4 + i4] = acc[mt][1];
    }
    __syncthreads();
    if (tid < MT) {
        float s = 0.f;
        #pragma unroll
        for (int k = 0; k < 16; ++k) s += sp[tid][k];
        g_Srow2[h][m0 + tid] = s;
    }
}

// ---------------- kernel 4a: assemble row sums, high-MLP version -------------
// 256 blocks x 256 threads; 32 rows/block; 8 d-groups of 8 slots, fully unrolled.
__global__ void __launch_bounds__(256) k_final1() {
    __shared__ float sredf[8][32];
    const int tid = threadIdx.x;
    const int r = tid & 31;          // row within block (coalesced)
    const int q = tid >> 5;          // 0..7 (d-group)
    const int row = blockIdx.x * 32 + r;

    float s = 0.f;
    const int d0 = q * 8;
    #pragma unroll
    for (int k = 0; k < 8; ++k) {
        int d = d0 + k;
        if (d < 63) s += g_colh[0][d][row] + g_colh[1][d][row];
    }
    if (q == 7 && row >= NB) s += g_colh[0][63][row] + g_colh[1][63][row];
    if (q == 0) s += g_Srow2[0][row] + g_Srow2[1][row];
    sredf[q][r] = s;
    __syncthreads();

    if (tid < 32) {
        float S = 0.f;
        #pragma unroll
        for (int k = 0; k < 8; ++k) S += sredf[k][tid];
        int rw = blockIdx.x * 32 + tid;
        double t = 2.0 + (double)logf(S) - (double)g_pos[rw];
        #pragma unroll
        for (int o = 16; o; o >>= 1)
            t += __shfl_xor_sync(0xffffffffu, t, o);
        if (tid == 0) g_part[blockIdx.x] = t;
    }
}

// ---------------- kernel 4b: final combine -----------------------------------
__global__ void __launch_bounds__(32) k_final2(float* out) {
    int tid = threadIdx.x;
    double t = 0.0;
    #pragma unroll
    for (int k = 0; k < 8; ++k) t += g_part[tid + 32 * k];
    #pragma unroll
    for (int o = 16; o; o >>= 1)
        t += __shfl_xor_sync(0xffffffffu, t, o);
    if (tid == 0) out[0] = (float)(t / (double)NN);
}

extern "C" void kernel_launch(void* const* d_in, const int* in_sizes, int n_in,
                              void* d_out, int out_size) {
    const float* zi = (const float*)d_in[0];
    const float* zj = (const float*)d_in[1];
    float* out = (float*)d_out;
    (void)in_sizes; (void)n_in; (void)out_size;

    k_normalize<<<NN / 8, 256>>>(zi, zj);
    k_pos<<<NB / 8, 256>>>(zi, zj);
    k_simexp<<<256, 256>>>();
    k_final1<<<256, 256>>>();
    k_final2<<<1, 32>>>(out);
}